// round 3
// baseline (speedup 1.0000x reference)
#include <cuda_runtime.h>
#include <math.h>

#define NB   8192   // batch tokens
#define HID  2048   // hidden
#define CD   256    // controller dim
#define KC   4096   // 2*HID

// Scratch for ctrl activations (8 MB) — static device array per allocation rules.
__device__ float g_ctrl[(size_t)NB * CD];

__device__ __forceinline__ float sigm(float x) { return 1.0f / (1.0f + expf(-x)); }

// ---------------------------------------------------------------------------
// Kernel 1: ctrl = silu([h | v] @ W_in^T + b_in)   M=8192, N=256, K=4096
// BM=64, BN=64, BK=32, TM=TN=4, 256 threads
// ---------------------------------------------------------------------------
__global__ __launch_bounds__(256) void k1_gemm_silu(
    const float* __restrict__ h, const float* __restrict__ v,
    const float* __restrict__ W_in, const float* __restrict__ b_in)
{
    __shared__ float As[32][68];
    __shared__ float Bs[32][68];
    const int m0 = blockIdx.y * 64;
    const int n0 = blockIdx.x * 64;
    const int t  = threadIdx.x;
    const int tx = t & 15, ty = t >> 4;
    float acc[4][4] = {};

    for (int k0 = 0; k0 < KC; k0 += 32) {
        #pragma unroll
        for (int it = 0; it < 2; it++) {
            int idx = t + it * 256;
            int m  = idx >> 3;
            int kk = (idx & 7) << 2;
            int gk = k0 + kk;
            const float* src = (gk < HID) ? (h + (size_t)(m0 + m) * HID + gk)
                                          : (v + (size_t)(m0 + m) * HID + (gk - HID));
            float4 a4 = *(const float4*)src;
            As[kk+0][m] = a4.x; As[kk+1][m] = a4.y; As[kk+2][m] = a4.z; As[kk+3][m] = a4.w;
        }
        #pragma unroll
        for (int it = 0; it < 2; it++) {
            int idx = t + it * 256;
            int n  = idx >> 3;
            int kk = (idx & 7) << 2;
            float4 b4 = *(const float4*)(W_in + (size_t)(n0 + n) * KC + k0 + kk);
            Bs[kk+0][n] = b4.x; Bs[kk+1][n] = b4.y; Bs[kk+2][n] = b4.z; Bs[kk+3][n] = b4.w;
        }
        __syncthreads();
        #pragma unroll 16
        for (int k = 0; k < 32; k++) {
            float4 a4 = *(const float4*)&As[k][ty * 4];
            float4 b4 = *(const float4*)&Bs[k][tx * 4];
            float ar[4] = {a4.x, a4.y, a4.z, a4.w};
            float br[4] = {b4.x, b4.y, b4.z, b4.w};
            #pragma unroll
            for (int i = 0; i < 4; i++)
                #pragma unroll
                for (int j = 0; j < 4; j++)
                    acc[i][j] = fmaf(ar[i], br[j], acc[i][j]);
        }
        __syncthreads();
    }
    #pragma unroll
    for (int i = 0; i < 4; i++) {
        int m = m0 + ty * 4 + i;
        #pragma unroll
        for (int j = 0; j < 4; j++) {
            int n = n0 + tx * 4 + j;
            float c = acc[i][j] + b_in[n];
            g_ctrl[(size_t)m * CD + n] = c * sigm(c);
        }
    }
}

// ---------------------------------------------------------------------------
// Kernel 2: mu_contextual = mu + h @ W_mu^T   M=8192, N=2048, K=2048
// BM=128, BN=128, BK=32, TM=TN=8, 256 threads
// ---------------------------------------------------------------------------
__global__ __launch_bounds__(256, 2) void k2_gemm_mu(
    const float* __restrict__ h, const float* __restrict__ W_mu,
    const float* __restrict__ mu, float* __restrict__ mu_out)
{
    __shared__ float As[32][132];
    __shared__ float Bs[32][132];
    const int m0 = blockIdx.y * 128;
    const int n0 = blockIdx.x * 128;
    const int t  = threadIdx.x;
    const int tx = t & 15, ty = t >> 4;
    float acc[8][8] = {};

    for (int k0 = 0; k0 < HID; k0 += 32) {
        #pragma unroll
        for (int it = 0; it < 4; it++) {
            int idx = t + it * 256;
            int r  = idx >> 3;
            int kk = (idx & 7) << 2;
            float4 a4 = *(const float4*)(h    + (size_t)(m0 + r) * HID + k0 + kk);
            As[kk+0][r] = a4.x; As[kk+1][r] = a4.y; As[kk+2][r] = a4.z; As[kk+3][r] = a4.w;
            float4 b4 = *(const float4*)(W_mu + (size_t)(n0 + r) * HID + k0 + kk);
            Bs[kk+0][r] = b4.x; Bs[kk+1][r] = b4.y; Bs[kk+2][r] = b4.z; Bs[kk+3][r] = b4.w;
        }
        __syncthreads();
        #pragma unroll 8
        for (int k = 0; k < 32; k++) {
            float a[8], b[8];
            *(float4*)&a[0] = *(const float4*)&As[k][ty * 8];
            *(float4*)&a[4] = *(const float4*)&As[k][ty * 8 + 4];
            *(float4*)&b[0] = *(const float4*)&Bs[k][tx * 8];
            *(float4*)&b[4] = *(const float4*)&Bs[k][tx * 8 + 4];
            #pragma unroll
            for (int i = 0; i < 8; i++)
                #pragma unroll
                for (int j = 0; j < 8; j++)
                    acc[i][j] = fmaf(a[i], b[j], acc[i][j]);
        }
        __syncthreads();
    }
    #pragma unroll
    for (int i = 0; i < 8; i++) {
        int m = m0 + ty * 8 + i;
        #pragma unroll
        for (int jv = 0; jv < 2; jv++) {
            int n = n0 + tx * 8 + jv * 4;
            float4 o;
            o.x = acc[i][jv*4+0] + mu[n+0];
            o.y = acc[i][jv*4+1] + mu[n+1];
            o.z = acc[i][jv*4+2] + mu[n+2];
            o.w = acc[i][jv*4+3] + mu[n+3];
            *(float4*)(mu_out + (size_t)m * HID + n) = o;
        }
    }
}

// ---------------------------------------------------------------------------
// Kernel 3: ctrl_out (3 gate columns) + full dynamics epilogue
// M=8192, N=2048 (per gate), K=256.  BM=128, BN=32, BK=32, TM=8, TN=2 x3 gates
// ---------------------------------------------------------------------------
__global__ __launch_bounds__(256, 2) void k3_gemm_final(
    const float* __restrict__ h, const float* __restrict__ v,
    const float* __restrict__ W_out, const float* __restrict__ b_out,
    const float* __restrict__ mu_out,
    float* __restrict__ h_next, float* __restrict__ v_next)
{
    __shared__ float Cs[32][132];
    __shared__ float Wa[32][36];
    __shared__ float Wb[32][36];
    __shared__ float Wg[32][36];
    const int m0 = blockIdx.y * 128;
    const int n0 = blockIdx.x * 32;
    const int t  = threadIdx.x;
    const int tx = t & 15, ty = t >> 4;
    float aa[8][2] = {}, ab[8][2] = {}, ag[8][2] = {};

    for (int k0 = 0; k0 < CD; k0 += 32) {
        #pragma unroll
        for (int it = 0; it < 4; it++) {
            int idx = t + it * 256;
            int m  = idx >> 3;
            int kk = (idx & 7) << 2;
            float4 c4 = *(const float4*)(g_ctrl + (size_t)(m0 + m) * CD + k0 + kk);
            Cs[kk+0][m] = c4.x; Cs[kk+1][m] = c4.y; Cs[kk+2][m] = c4.z; Cs[kk+3][m] = c4.w;
        }
        {
            int n  = t >> 3;            // 0..31
            int kk = (t & 7) << 2;
            float4 w4;
            w4 = *(const float4*)(W_out + (size_t)(n0 + n) * CD + k0 + kk);
            Wa[kk+0][n] = w4.x; Wa[kk+1][n] = w4.y; Wa[kk+2][n] = w4.z; Wa[kk+3][n] = w4.w;
            w4 = *(const float4*)(W_out + (size_t)(HID + n0 + n) * CD + k0 + kk);
            Wb[kk+0][n] = w4.x; Wb[kk+1][n] = w4.y; Wb[kk+2][n] = w4.z; Wb[kk+3][n] = w4.w;
            w4 = *(const float4*)(W_out + (size_t)(2 * HID + n0 + n) * CD + k0 + kk);
            Wg[kk+0][n] = w4.x; Wg[kk+1][n] = w4.y; Wg[kk+2][n] = w4.z; Wg[kk+3][n] = w4.w;
        }
        __syncthreads();
        #pragma unroll 8
        for (int k = 0; k < 32; k++) {
            float c[8];
            *(float4*)&c[0] = *(const float4*)&Cs[k][ty * 8];
            *(float4*)&c[4] = *(const float4*)&Cs[k][ty * 8 + 4];
            float wa0 = Wa[k][tx*2], wa1 = Wa[k][tx*2+1];
            float wb0 = Wb[k][tx*2], wb1 = Wb[k][tx*2+1];
            float wg0 = Wg[k][tx*2], wg1 = Wg[k][tx*2+1];
            #pragma unroll
            for (int i = 0; i < 8; i++) {
                aa[i][0] = fmaf(c[i], wa0, aa[i][0]);
                aa[i][1] = fmaf(c[i], wa1, aa[i][1]);
                ab[i][0] = fmaf(c[i], wb0, ab[i][0]);
                ab[i][1] = fmaf(c[i], wb1, ab[i][1]);
                ag[i][0] = fmaf(c[i], wg0, ag[i][0]);
                ag[i][1] = fmaf(c[i], wg1, ag[i][1]);
            }
        }
        __syncthreads();
    }
    #pragma unroll
    for (int i = 0; i < 8; i++) {
        int m = m0 + ty * 8 + i;
        #pragma unroll
        for (int j = 0; j < 2; j++) {
            int n = n0 + tx * 2 + j;
            float ar = aa[i][j] + b_out[n];
            float br = ab[i][j] + b_out[HID + n];
            float gr = ag[i][j] + b_out[2 * HID + n];
            float alpha = sigm(ar);
            float sp    = fmaxf(br, 0.f) + log1pf(expf(-fabsf(br)));  // stable softplus
            float beta  = fminf(sp, 2.0f);
            float gate  = sigm(gr);
            size_t off = (size_t)m * HID + n;
            float hv = h[off];
            float vv = v[off];
            float mc = mu_out[off];
            float err = hv - mc;
            float vn = alpha * vv - beta * err;
            vn = fminf(fmaxf(vn, -10.f), 10.f);
            float hn = hv + 0.1f * gate * vn;
            h_next[off] = hn;
            v_next[off] = vn;
        }
    }
}

// ---------------------------------------------------------------------------
extern "C" void kernel_launch(void* const* d_in, const int* in_sizes, int n_in,
                              void* d_out, int out_size)
{
    const float* h     = (const float*)d_in[0];
    const float* v     = (const float*)d_in[1];
    const float* W_in  = (const float*)d_in[2];
    const float* b_in  = (const float*)d_in[3];
    const float* W_out = (const float*)d_in[4];
    const float* b_out = (const float*)d_in[5];
    const float* W_mu  = (const float*)d_in[6];
    const float* mu    = (const float*)d_in[7];

    float* out    = (float*)d_out;
    float* h_next = out;                               // [B, H]
    float* v_next = out + (size_t)NB * HID;            // [B, H]
    float* mu_out = out + 2 * (size_t)NB * HID;        // [B, H]

    k1_gemm_silu <<<dim3(CD / 64,  NB / 64),  256>>>(h, v, W_in, b_in);
    k2_gemm_mu   <<<dim3(HID / 128, NB / 128), 256>>>(h, W_mu, mu, mu_out);
    k3_gemm_final<<<dim3(HID / 32,  NB / 128), 256>>>(h, v, W_out, b_out, mu_out,
                                                      h_next, v_next);
}

// round 7
// speedup vs baseline: 2.0180x; 2.0180x over previous
#include <cuda_runtime.h>
#include <cuda_bf16.h>
#include <stdint.h>
#include <math.h>

#define NB  8192
#define HID 2048
#define CD  256
#define KC  4096

// ---------------- static scratch (allocation-free) ----------------
__device__ __align__(128) __nv_bfloat16 g_hhi[(size_t)NB * HID];
__device__ __align__(128) __nv_bfloat16 g_hlo[(size_t)NB * HID];
__device__ __align__(128) __nv_bfloat16 g_vhi[(size_t)NB * HID];
__device__ __align__(128) __nv_bfloat16 g_vlo[(size_t)NB * HID];
__device__ __align__(128) __nv_bfloat16 g_Wmu_hi[(size_t)HID * HID];
__device__ __align__(128) __nv_bfloat16 g_Wmu_lo[(size_t)HID * HID];
__device__ __align__(128) __nv_bfloat16 g_Win_hi[(size_t)CD * KC];
__device__ __align__(128) __nv_bfloat16 g_Win_lo[(size_t)CD * KC];
__device__ __align__(128) __nv_bfloat16 g_Wout_hi[(size_t)3 * HID * CD];
__device__ __align__(128) __nv_bfloat16 g_Wout_lo[(size_t)3 * HID * CD];
__device__ __align__(128) __nv_bfloat16 g_chi[(size_t)NB * CD];
__device__ __align__(128) __nv_bfloat16 g_clo[(size_t)NB * CD];

// ---------------- helpers ----------------
__device__ __forceinline__ uint32_t smem_u32(const void* p) {
    uint32_t a;
    asm("{ .reg .u64 t; cvta.to.shared.u64 t, %1; cvt.u32.u64 %0, t; }" : "=r"(a) : "l"(p));
    return a;
}
__device__ __forceinline__ float sigm(float x) { return 1.0f / (1.0f + expf(-x)); }

#define CPA16(s, g) asm volatile("cp.async.cg.shared.global [%0], [%1], 16;" :: "r"(s), "l"(g))
#define CPC()       asm volatile("cp.async.commit_group;")
#define CPW(n)      asm volatile("cp.async.wait_group %0;" :: "n"(n))

__device__ __forceinline__ void ldsm4(uint32_t* d, uint32_t a) {
    asm volatile("ldmatrix.sync.aligned.m8n8.x4.shared.b16 {%0,%1,%2,%3}, [%4];"
                 : "=r"(d[0]), "=r"(d[1]), "=r"(d[2]), "=r"(d[3]) : "r"(a));
}
__device__ __forceinline__ void mma_bf16(float* c, const uint32_t* a, uint32_t b0, uint32_t b1) {
    asm volatile("mma.sync.aligned.m16n8k16.row.col.f32.bf16.bf16.f32 "
                 "{%0,%1,%2,%3},{%4,%5,%6,%7},{%8,%9},{%0,%1,%2,%3};"
                 : "+f"(c[0]), "+f"(c[1]), "+f"(c[2]), "+f"(c[3])
                 : "r"(a[0]), "r"(a[1]), "r"(a[2]), "r"(a[3]), "r"(b0), "r"(b1));
}

// ---------------- fp32 -> bf16 hi/lo split ----------------
__global__ __launch_bounds__(256) void k_conv(const float* __restrict__ s,
                                              __nv_bfloat16* __restrict__ hi,
                                              __nv_bfloat16* __restrict__ lo, int n)
{
    int i = (blockIdx.x * 256 + threadIdx.x) * 4;
    if (i >= n) return;
    float4 x = *(const float4*)(s + i);
    __nv_bfloat16 h0 = __float2bfloat16(x.x), h1 = __float2bfloat16(x.y);
    __nv_bfloat16 h2 = __float2bfloat16(x.z), h3 = __float2bfloat16(x.w);
    __nv_bfloat16 l0 = __float2bfloat16(x.x - __bfloat162float(h0));
    __nv_bfloat16 l1 = __float2bfloat16(x.y - __bfloat162float(h1));
    __nv_bfloat16 l2 = __float2bfloat16(x.z - __bfloat162float(h2));
    __nv_bfloat16 l3 = __float2bfloat16(x.w - __bfloat162float(h3));
    __nv_bfloat162* H = (__nv_bfloat162*)(hi + i);
    __nv_bfloat162* L = (__nv_bfloat162*)(lo + i);
    H[0] = __halves2bfloat162(h0, h1); H[1] = __halves2bfloat162(h2, h3);
    L[0] = __halves2bfloat162(l0, l1); L[1] = __halves2bfloat162(l2, l3);
}

// =============================================================================
// GEMM core (k1/k2): block 128x128, 8 warps 2(M)x4(N), warp tile 64x32,
// K stage 32, 80B-padded smem rows. Both A and B tiles are K-contiguous, so
// BOTH use non-trans ldmatrix (B fragment row index = n = addressed smem row).
// =============================================================================

#define COMPUTE_STAGE_128x128(As, Bs)                                          \
    _Pragma("unroll")                                                          \
    for (int kk = 0; kk < 32; kk += 16) {                                      \
        uint32_t ah[4][4], al[4][4];                                           \
        uint32_t aoff = (As) + wm * 5120 + (lane & 15) * 80 + (lane >> 4) * 16 + kk * 2; \
        _Pragma("unroll")                                                      \
        for (int mt = 0; mt < 4; mt++) {                                       \
            ldsm4(ah[mt], aoff + mt * 1280);                                   \
            ldsm4(al[mt], aoff + 10240 + mt * 1280);                           \
        }                                                                      \
        uint32_t boff = (Bs) + wn * 2560 + ((lane & 7) + ((lane >> 3) & 1) * 8) * 80 \
                        + (lane >> 4) * 16 + kk * 2;                           \
        _Pragma("unroll")                                                      \
        for (int np = 0; np < 2; np++) {                                       \
            uint32_t bh[4], bl[4];                                             \
            ldsm4(bh, boff + np * 1280);                                       \
            ldsm4(bl, boff + 10240 + np * 1280);                               \
            _Pragma("unroll")                                                  \
            for (int mt = 0; mt < 4; mt++) {                                   \
                mma_bf16(c[mt][np*2],   ah[mt], bh[0], bh[2]);                 \
                mma_bf16(c[mt][np*2+1], ah[mt], bh[1], bh[3]);                 \
                mma_bf16(c[mt][np*2],   ah[mt], bl[0], bl[2]);                 \
                mma_bf16(c[mt][np*2+1], ah[mt], bl[1], bl[3]);                 \
                mma_bf16(c[mt][np*2],   al[mt], bh[0], bh[2]);                 \
                mma_bf16(c[mt][np*2+1], al[mt], bh[1], bh[3]);                 \
            }                                                                  \
        }                                                                      \
    }

// ---------------- k1: ctrl = silu([h|v] @ W_in^T + b_in) -> bf16 hi/lo ------
__global__ __launch_bounds__(256, 1) void k1_mma(const float* __restrict__ b_in)
{
    extern __shared__ char smem[];
    const int t = threadIdx.x, lane = t & 31, wid = t >> 5;
    const int wm = wid >> 2, wn = wid & 3;
    const int m0 = blockIdx.y * 128, n0 = blockIdx.x * 128;
    uint32_t sb = smem_u32(smem);
    float c[4][4][4] = {};

    auto load_stage = [&](int i, int buf) {
        int k0 = i * 32;
        const __nv_bfloat16 *ah, *al; int kc;
        if (k0 < HID) { ah = g_hhi; al = g_hlo; kc = k0; }
        else          { ah = g_vhi; al = g_vlo; kc = k0 - HID; }
        uint32_t dst = sb + buf * 40960;
        #pragma unroll
        for (int it = 0; it < 8; it++) {
            int idx = t + it * 256;
            int region = idx >> 10, part = (idx >> 9) & 1;
            int row = (idx >> 2) & 127, seg = idx & 3;
            const __nv_bfloat16* gp;
            uint32_t s;
            if (region == 0) {
                gp = (part ? al : ah) + (size_t)(m0 + row) * HID + kc + seg * 8;
                s = dst + part * 10240 + row * 80 + seg * 16;
            } else {
                gp = (part ? g_Win_lo : g_Win_hi) + (size_t)(n0 + row) * KC + k0 + seg * 8;
                s = dst + 20480 + part * 10240 + row * 80 + seg * 16;
            }
            CPA16(s, gp);
        }
        CPC();
    };

    const int NS = KC / 32;
    load_stage(0, 0);
    for (int i = 0; i < NS; i++) {
        int buf = i & 1;
        if (i + 1 < NS) { load_stage(i + 1, buf ^ 1); CPW(1); } else { CPW(0); }
        __syncthreads();
        uint32_t As = sb + buf * 40960, Bs = As + 20480;
        COMPUTE_STAGE_128x128(As, Bs);
        __syncthreads();
    }

    const int gr = lane >> 2, gc = (lane & 3) * 2;
    #pragma unroll
    for (int mt = 0; mt < 4; mt++)
        #pragma unroll
        for (int half = 0; half < 2; half++) {
            int row = m0 + wm * 64 + mt * 16 + gr + half * 8;
            #pragma unroll
            for (int nt = 0; nt < 4; nt++) {
                int ng = n0 + wn * 32 + nt * 8 + gc;
                float s0 = c[mt][nt][half * 2]     + b_in[ng];
                float s1 = c[mt][nt][half * 2 + 1] + b_in[ng + 1];
                s0 = s0 * sigm(s0); s1 = s1 * sigm(s1);
                __nv_bfloat16 h0 = __float2bfloat16(s0), h1 = __float2bfloat16(s1);
                __nv_bfloat16 l0 = __float2bfloat16(s0 - __bfloat162float(h0));
                __nv_bfloat16 l1 = __float2bfloat16(s1 - __bfloat162float(h1));
                size_t o = (size_t)row * CD + ng;
                *(__nv_bfloat162*)(g_chi + o) = __halves2bfloat162(h0, h1);
                *(__nv_bfloat162*)(g_clo + o) = __halves2bfloat162(l0, l1);
            }
        }
}

// ---------------- k2: mu_out = mu + h @ W_mu^T ------------------------------
__global__ __launch_bounds__(256, 1) void k2_mma(const float* __restrict__ mu,
                                                 float* __restrict__ mu_out)
{
    extern __shared__ char smem[];
    const int t = threadIdx.x, lane = t & 31, wid = t >> 5;
    const int wm = wid >> 2, wn = wid & 3;
    const int m0 = blockIdx.y * 128, n0 = blockIdx.x * 128;
    uint32_t sb = smem_u32(smem);
    float c[4][4][4] = {};

    auto load_stage = [&](int i, int buf) {
        int k0 = i * 32;
        uint32_t dst = sb + buf * 40960;
        #pragma unroll
        for (int it = 0; it < 8; it++) {
            int idx = t + it * 256;
            int region = idx >> 10, part = (idx >> 9) & 1;
            int row = (idx >> 2) & 127, seg = idx & 3;
            const __nv_bfloat16* gp;
            uint32_t s;
            if (region == 0) {
                gp = (part ? g_hlo : g_hhi) + (size_t)(m0 + row) * HID + k0 + seg * 8;
                s = dst + part * 10240 + row * 80 + seg * 16;
            } else {
                gp = (part ? g_Wmu_lo : g_Wmu_hi) + (size_t)(n0 + row) * HID + k0 + seg * 8;
                s = dst + 20480 + part * 10240 + row * 80 + seg * 16;
            }
            CPA16(s, gp);
        }
        CPC();
    };

    const int NS = HID / 32;
    load_stage(0, 0);
    for (int i = 0; i < NS; i++) {
        int buf = i & 1;
        if (i + 1 < NS) { load_stage(i + 1, buf ^ 1); CPW(1); } else { CPW(0); }
        __syncthreads();
        uint32_t As = sb + buf * 40960, Bs = As + 20480;
        COMPUTE_STAGE_128x128(As, Bs);
        __syncthreads();
    }

    const int gr = lane >> 2, gc = (lane & 3) * 2;
    #pragma unroll
    for (int mt = 0; mt < 4; mt++)
        #pragma unroll
        for (int half = 0; half < 2; half++) {
            int row = m0 + wm * 64 + mt * 16 + gr + half * 8;
            #pragma unroll
            for (int nt = 0; nt < 4; nt++) {
                int ng = n0 + wn * 32 + nt * 8 + gc;
                float2 o;
                o.x = c[mt][nt][half * 2]     + mu[ng];
                o.y = c[mt][nt][half * 2 + 1] + mu[ng + 1];
                *(float2*)(mu_out + (size_t)row * HID + ng) = o;
            }
        }
}

// ---------------- k3: 3-gate GEMM (K=256) + fused dynamics epilogue ---------
__global__ __launch_bounds__(256, 1) void k3_mma(
    const float* __restrict__ h, const float* __restrict__ v,
    const float* __restrict__ b_out, const float* __restrict__ mu_out,
    float* __restrict__ h_next, float* __restrict__ v_next)
{
    extern __shared__ char smem[];
    const int t = threadIdx.x, lane = t & 31, wid = t >> 5;
    const int wm = wid >> 2, wn = wid & 3;
    const int m0 = blockIdx.y * 128, n0 = blockIdx.x * 64;
    uint32_t sb = smem_u32(smem);
    float c[3][4][2][4] = {};

    auto load_stage = [&](int i, int buf) {
        int k0 = i * 32;
        uint32_t dst = sb + buf * 51200;
        #pragma unroll
        for (int it = 0; it < 10; it++) {
            int idx = t + it * 256;
            const __nv_bfloat16* gp;
            uint32_t s;
            if (idx < 1024) {
                int part = (idx >> 9) & 1, row = (idx >> 2) & 127, seg = idx & 3;
                gp = (part ? g_clo : g_chi) + (size_t)(m0 + row) * CD + k0 + seg * 8;
                s = dst + part * 10240 + row * 80 + seg * 16;
            } else {
                int j = idx - 1024;
                int part = j >= 768; int j2 = j - part * 768;
                int row = j2 >> 2, seg = j2 & 3;
                int g = row >> 6, rg = row & 63;
                gp = (part ? g_Wout_lo : g_Wout_hi)
                     + (size_t)(g * HID + n0 + rg) * CD + k0 + seg * 8;
                s = dst + 20480 + part * 15360 + g * 5120 + rg * 80 + seg * 16;
            }
            CPA16(s, gp);
        }
        CPC();
    };

    const int NS = CD / 32;  // 8
    load_stage(0, 0);
    for (int i = 0; i < NS; i++) {
        int buf = i & 1;
        if (i + 1 < NS) { load_stage(i + 1, buf ^ 1); CPW(1); } else { CPW(0); }
        __syncthreads();
        uint32_t As = sb + buf * 51200, Bs = As + 20480;
        #pragma unroll
        for (int kk = 0; kk < 32; kk += 16) {
            uint32_t ah[4][4], al[4][4];
            uint32_t aoff = As + wm * 5120 + (lane & 15) * 80 + (lane >> 4) * 16 + kk * 2;
            #pragma unroll
            for (int mt = 0; mt < 4; mt++) {
                ldsm4(ah[mt], aoff + mt * 1280);
                ldsm4(al[mt], aoff + 10240 + mt * 1280);
            }
            uint32_t boff = Bs + wn * 1280 + ((lane & 7) + ((lane >> 3) & 1) * 8) * 80
                            + (lane >> 4) * 16 + kk * 2;
            #pragma unroll
            for (int g = 0; g < 3; g++) {
                uint32_t bh[4], bl[4];
                ldsm4(bh, boff + g * 5120);
                ldsm4(bl, boff + 15360 + g * 5120);
                #pragma unroll
                for (int mt = 0; mt < 4; mt++) {
                    mma_bf16(c[g][mt][0], ah[mt], bh[0], bh[2]);
                    mma_bf16(c[g][mt][1], ah[mt], bh[1], bh[3]);
                    mma_bf16(c[g][mt][0], ah[mt], bl[0], bl[2]);
                    mma_bf16(c[g][mt][1], ah[mt], bl[1], bl[3]);
                    mma_bf16(c[g][mt][0], al[mt], bh[0], bh[2]);
                    mma_bf16(c[g][mt][1], al[mt], bh[1], bh[3]);
                }
            }
        }
        __syncthreads();
    }

    const int gr = lane >> 2, gc = (lane & 3) * 2;
    #pragma unroll
    for (int mt = 0; mt < 4; mt++)
        #pragma unroll
        for (int half = 0; half < 2; half++) {
            int row = m0 + wm * 64 + mt * 16 + gr + half * 8;
            size_t rb = (size_t)row * HID;
            #pragma unroll
            for (int nt = 0; nt < 2; nt++) {
                int ng = n0 + wn * 16 + nt * 8 + gc;
                size_t o = rb + ng;
                float a0 = c[0][mt][nt][half*2]   + b_out[ng];
                float a1 = c[0][mt][nt][half*2+1] + b_out[ng + 1];
                float b0 = c[1][mt][nt][half*2]   + b_out[HID + ng];
                float b1 = c[1][mt][nt][half*2+1] + b_out[HID + ng + 1];
                float g0 = c[2][mt][nt][half*2]   + b_out[2 * HID + ng];
                float g1 = c[2][mt][nt][half*2+1] + b_out[2 * HID + ng + 1];
                float al0 = sigm(a0), al1 = sigm(a1);
                float be0 = fminf(fmaxf(b0, 0.f) + log1pf(expf(-fabsf(b0))), 2.0f);
                float be1 = fminf(fmaxf(b1, 0.f) + log1pf(expf(-fabsf(b1))), 2.0f);
                float gt0 = sigm(g0), gt1 = sigm(g1);
                float2 hv = *(const float2*)(h + o);
                float2 vv = *(const float2*)(v + o);
                float2 mc = *(const float2*)(mu_out + o);
                float vn0 = al0 * vv.x - be0 * (hv.x - mc.x);
                float vn1 = al1 * vv.y - be1 * (hv.y - mc.y);
                vn0 = fminf(fmaxf(vn0, -10.f), 10.f);
                vn1 = fminf(fmaxf(vn1, -10.f), 10.f);
                float2 hn = { hv.x + 0.1f * gt0 * vn0, hv.y + 0.1f * gt1 * vn1 };
                float2 vn = { vn0, vn1 };
                *(float2*)(h_next + o) = hn;
                *(float2*)(v_next + o) = vn;
            }
        }
}

// ---------------- launch ----------------
extern "C" void kernel_launch(void* const* d_in, const int* in_sizes, int n_in,
                              void* d_out, int out_size)
{
    const float* h     = (const float*)d_in[0];
    const float* v     = (const float*)d_in[1];
    const float* W_in  = (const float*)d_in[2];
    const float* b_in  = (const float*)d_in[3];
    const float* W_out = (const float*)d_in[4];
    const float* b_out = (const float*)d_in[5];
    const float* W_mu  = (const float*)d_in[6];
    const float* mu    = (const float*)d_in[7];

    float* out    = (float*)d_out;
    float* h_next = out;
    float* v_next = out + (size_t)NB * HID;
    float* mu_out = out + 2 * (size_t)NB * HID;

    cudaFuncSetAttribute(k1_mma, cudaFuncAttributeMaxDynamicSharedMemorySize, 2 * 40960);
    cudaFuncSetAttribute(k2_mma, cudaFuncAttributeMaxDynamicSharedMemorySize, 2 * 40960);
    cudaFuncSetAttribute(k3_mma, cudaFuncAttributeMaxDynamicSharedMemorySize, 2 * 51200);

    __nv_bfloat16 *hhi, *hlo, *vhi, *vlo, *wmh, *wml, *wih, *wil, *woh, *wol;
    cudaGetSymbolAddress((void**)&hhi, g_hhi);   cudaGetSymbolAddress((void**)&hlo, g_hlo);
    cudaGetSymbolAddress((void**)&vhi, g_vhi);   cudaGetSymbolAddress((void**)&vlo, g_vlo);
    cudaGetSymbolAddress((void**)&wmh, g_Wmu_hi); cudaGetSymbolAddress((void**)&wml, g_Wmu_lo);
    cudaGetSymbolAddress((void**)&wih, g_Win_hi); cudaGetSymbolAddress((void**)&wil, g_Win_lo);
    cudaGetSymbolAddress((void**)&woh, g_Wout_hi); cudaGetSymbolAddress((void**)&wol, g_Wout_lo);

    const int nh  = NB * HID;
    const int nwm = HID * HID;
    const int nwi = CD * KC;
    const int nwo = 3 * HID * CD;
    k_conv<<<nh  / 4 / 256, 256>>>(h,     hhi, hlo, nh);
    k_conv<<<nh  / 4 / 256, 256>>>(v,     vhi, vlo, nh);
    k_conv<<<nwm / 4 / 256, 256>>>(W_mu,  wmh, wml, nwm);
    k_conv<<<nwi / 4 / 256, 256>>>(W_in,  wih, wil, nwi);
    k_conv<<<nwo / 4 / 256, 256>>>(W_out, woh, wol, nwo);

    k1_mma<<<dim3(CD / 128,  NB / 128), 256, 2 * 40960>>>(b_in);
    k2_mma<<<dim3(HID / 128, NB / 128), 256, 2 * 40960>>>(mu, mu_out);
    k3_mma<<<dim3(HID / 64,  NB / 128), 256, 2 * 51200>>>(h, v, b_out, mu_out,
                                                          h_next, v_next);
}

// round 8
// speedup vs baseline: 2.4908x; 1.2343x over previous
#include <cuda_runtime.h>
#include <cuda_bf16.h>
#include <stdint.h>
#include <math.h>

#define NB  8192
#define HID 2048
#define CD  256
#define KC  4096

// ---------------- static scratch (allocation-free) ----------------
__device__ __align__(128) __nv_bfloat16 g_hhi[(size_t)NB * HID];
__device__ __align__(128) __nv_bfloat16 g_hlo[(size_t)NB * HID];
__device__ __align__(128) __nv_bfloat16 g_vhi[(size_t)NB * HID];
__device__ __align__(128) __nv_bfloat16 g_Wmu_hi[(size_t)HID * HID];
__device__ __align__(128) __nv_bfloat16 g_Wmu_lo[(size_t)HID * HID];
__device__ __align__(128) __nv_bfloat16 g_Win_hi[(size_t)CD * KC];
__device__ __align__(128) __nv_bfloat16 g_Wout_hi[(size_t)3 * HID * CD];
__device__ __align__(128) __nv_bfloat16 g_chi[(size_t)NB * CD];

// ---------------- helpers ----------------
__device__ __forceinline__ uint32_t smem_u32(const void* p) {
    uint32_t a;
    asm("{ .reg .u64 t; cvta.to.shared.u64 t, %1; cvt.u32.u64 %0, t; }" : "=r"(a) : "l"(p));
    return a;
}
__device__ __forceinline__ float sigm(float x) { return 1.0f / (1.0f + expf(-x)); }

#define CPA16(s, g) asm volatile("cp.async.cg.shared.global [%0], [%1], 16;" :: "r"(s), "l"(g))
#define CPC()       asm volatile("cp.async.commit_group;")
#define CPW(n)      asm volatile("cp.async.wait_group %0;" :: "n"(n))

__device__ __forceinline__ void ldsm4(uint32_t* d, uint32_t a) {
    asm volatile("ldmatrix.sync.aligned.m8n8.x4.shared.b16 {%0,%1,%2,%3}, [%4];"
                 : "=r"(d[0]), "=r"(d[1]), "=r"(d[2]), "=r"(d[3]) : "r"(a));
}
__device__ __forceinline__ void mma_bf16(float* c, const uint32_t* a, uint32_t b0, uint32_t b1) {
    asm volatile("mma.sync.aligned.m16n8k16.row.col.f32.bf16.bf16.f32 "
                 "{%0,%1,%2,%3},{%4,%5,%6,%7},{%8,%9},{%0,%1,%2,%3};"
                 : "+f"(c[0]), "+f"(c[1]), "+f"(c[2]), "+f"(c[3])
                 : "r"(a[0]), "r"(a[1]), "r"(a[2]), "r"(a[3]), "r"(b0), "r"(b1));
}

// ---------------- fp32 -> bf16 conversions ----------------
__global__ __launch_bounds__(256) void k_conv(const float* __restrict__ s,
                                              __nv_bfloat16* __restrict__ hi,
                                              __nv_bfloat16* __restrict__ lo, int n)
{
    int i = (blockIdx.x * 256 + threadIdx.x) * 4;
    if (i >= n) return;
    float4 x = *(const float4*)(s + i);
    __nv_bfloat16 h0 = __float2bfloat16(x.x), h1 = __float2bfloat16(x.y);
    __nv_bfloat16 h2 = __float2bfloat16(x.z), h3 = __float2bfloat16(x.w);
    __nv_bfloat16 l0 = __float2bfloat16(x.x - __bfloat162float(h0));
    __nv_bfloat16 l1 = __float2bfloat16(x.y - __bfloat162float(h1));
    __nv_bfloat16 l2 = __float2bfloat16(x.z - __bfloat162float(h2));
    __nv_bfloat16 l3 = __float2bfloat16(x.w - __bfloat162float(h3));
    __nv_bfloat162* H = (__nv_bfloat162*)(hi + i);
    __nv_bfloat162* L = (__nv_bfloat162*)(lo + i);
    H[0] = __halves2bfloat162(h0, h1); H[1] = __halves2bfloat162(h2, h3);
    L[0] = __halves2bfloat162(l0, l1); L[1] = __halves2bfloat162(l2, l3);
}

__global__ __launch_bounds__(256) void k_conv_hi(const float* __restrict__ s,
                                                 __nv_bfloat16* __restrict__ hi, int n)
{
    int i = (blockIdx.x * 256 + threadIdx.x) * 4;
    if (i >= n) return;
    float4 x = *(const float4*)(s + i);
    __nv_bfloat162* H = (__nv_bfloat162*)(hi + i);
    H[0] = __halves2bfloat162(__float2bfloat16(x.x), __float2bfloat16(x.y));
    H[1] = __halves2bfloat162(__float2bfloat16(x.z), __float2bfloat16(x.w));
}

// =============================================================================
// Geometry: block 128x128 (k1/k2) 8 warps 2(M)x4(N) warp tile 64x32;
// K stage 32; 80B-padded rows; non-trans ldmatrix both sides (K-contiguous).
// 3-stage cp.async pipeline with empty-commit tail.
// =============================================================================

// ---- 3-pass (hi/lo) compute, stage layout: Ahi Alo Bhi Blo each 10240 ----
#define COMPUTE_HL_128x128(As, Bs)                                             \
    _Pragma("unroll")                                                          \
    for (int kk = 0; kk < 32; kk += 16) {                                      \
        uint32_t ah[4][4], al[4][4];                                           \
        uint32_t aoff = (As) + wm * 5120 + (lane & 15) * 80 + (lane >> 4) * 16 + kk * 2; \
        _Pragma("unroll")                                                      \
        for (int mt = 0; mt < 4; mt++) {                                       \
            ldsm4(ah[mt], aoff + mt * 1280);                                   \
            ldsm4(al[mt], aoff + 10240 + mt * 1280);                           \
        }                                                                      \
        uint32_t boff = (Bs) + wn * 2560 + ((lane & 7) + ((lane >> 3) & 1) * 8) * 80 \
                        + (lane >> 4) * 16 + kk * 2;                           \
        _Pragma("unroll")                                                      \
        for (int np = 0; np < 2; np++) {                                       \
            uint32_t bh[4], bl[4];                                             \
            ldsm4(bh, boff + np * 1280);                                       \
            ldsm4(bl, boff + 10240 + np * 1280);                               \
            _Pragma("unroll")                                                  \
            for (int mt = 0; mt < 4; mt++) {                                   \
                mma_bf16(c[mt][np*2],   ah[mt], bh[0], bh[2]);                 \
                mma_bf16(c[mt][np*2+1], ah[mt], bh[1], bh[3]);                 \
                mma_bf16(c[mt][np*2],   ah[mt], bl[0], bl[2]);                 \
                mma_bf16(c[mt][np*2+1], ah[mt], bl[1], bl[3]);                 \
                mma_bf16(c[mt][np*2],   al[mt], bh[0], bh[2]);                 \
                mma_bf16(c[mt][np*2+1], al[mt], bh[1], bh[3]);                 \
            }                                                                  \
        }                                                                      \
    }

// ---- single-pass compute, stage layout: A(10240) B(10240) ----
#define COMPUTE_SP_128x128(As, Bs)                                             \
    _Pragma("unroll")                                                          \
    for (int kk = 0; kk < 32; kk += 16) {                                      \
        uint32_t ah[4][4];                                                     \
        uint32_t aoff = (As) + wm * 5120 + (lane & 15) * 80 + (lane >> 4) * 16 + kk * 2; \
        _Pragma("unroll")                                                      \
        for (int mt = 0; mt < 4; mt++) ldsm4(ah[mt], aoff + mt * 1280);        \
        uint32_t boff = (Bs) + wn * 2560 + ((lane & 7) + ((lane >> 3) & 1) * 8) * 80 \
                        + (lane >> 4) * 16 + kk * 2;                           \
        _Pragma("unroll")                                                      \
        for (int np = 0; np < 2; np++) {                                       \
            uint32_t bh[4];                                                    \
            ldsm4(bh, boff + np * 1280);                                       \
            _Pragma("unroll")                                                  \
            for (int mt = 0; mt < 4; mt++) {                                   \
                mma_bf16(c[mt][np*2],   ah[mt], bh[0], bh[2]);                 \
                mma_bf16(c[mt][np*2+1], ah[mt], bh[1], bh[3]);                 \
            }                                                                  \
        }                                                                      \
    }

// ---------------- k1: ctrl = silu([h|v] @ W_in^T + b_in), single-pass -------
__global__ __launch_bounds__(256, 1) void k1_mma(const float* __restrict__ b_in)
{
    extern __shared__ char smem[];
    const int t = threadIdx.x, lane = t & 31, wid = t >> 5;
    const int wm = wid >> 2, wn = wid & 3;
    const int m0 = blockIdx.y * 128, n0 = blockIdx.x * 128;
    uint32_t sb = smem_u32(smem);
    float c[4][4][4] = {};

    auto load_stage = [&](int i, int buf) {
        int k0 = i * 32;
        const __nv_bfloat16* ah; int kc;
        if (k0 < HID) { ah = g_hhi; kc = k0; } else { ah = g_vhi; kc = k0 - HID; }
        uint32_t dst = sb + buf * 20480;
        #pragma unroll
        for (int it = 0; it < 4; it++) {
            int idx = t + it * 256;
            const __nv_bfloat16* gp;
            uint32_t s;
            if (idx < 512) {
                int row = idx >> 2, seg = idx & 3;
                gp = ah + (size_t)(m0 + row) * HID + kc + seg * 8;
                s = dst + row * 80 + seg * 16;
            } else {
                int j = idx - 512, row = j >> 2, seg = j & 3;
                gp = g_Win_hi + (size_t)(n0 + row) * KC + k0 + seg * 8;
                s = dst + 10240 + row * 80 + seg * 16;
            }
            CPA16(s, gp);
        }
        CPC();
    };

    const int NS = KC / 32;
    load_stage(0, 0); load_stage(1, 1);
    for (int i = 0; i < NS; i++) {
        int buf = i % 3;
        if (i + 2 < NS) load_stage(i + 2, (i + 2) % 3); else CPC();
        CPW(2);
        __syncthreads();
        uint32_t As = sb + buf * 20480, Bs = As + 10240;
        COMPUTE_SP_128x128(As, Bs);
        __syncthreads();
    }

    const int gr = lane >> 2, gc = (lane & 3) * 2;
    #pragma unroll
    for (int mt = 0; mt < 4; mt++)
        #pragma unroll
        for (int half = 0; half < 2; half++) {
            int row = m0 + wm * 64 + mt * 16 + gr + half * 8;
            #pragma unroll
            for (int nt = 0; nt < 4; nt++) {
                int ng = n0 + wn * 32 + nt * 8 + gc;
                float s0 = c[mt][nt][half * 2]     + b_in[ng];
                float s1 = c[mt][nt][half * 2 + 1] + b_in[ng + 1];
                s0 = s0 * sigm(s0); s1 = s1 * sigm(s1);
                *(__nv_bfloat162*)(g_chi + (size_t)row * CD + ng) =
                    __halves2bfloat162(__float2bfloat16(s0), __float2bfloat16(s1));
            }
        }
}

// ---------------- k2: mu_out = mu + h @ W_mu^T (3-pass hi/lo) ---------------
__global__ __launch_bounds__(256, 1) void k2_mma(const float* __restrict__ mu,
                                                 float* __restrict__ mu_out)
{
    extern __shared__ char smem[];
    const int t = threadIdx.x, lane = t & 31, wid = t >> 5;
    const int wm = wid >> 2, wn = wid & 3;
    const int m0 = blockIdx.y * 128, n0 = blockIdx.x * 128;
    uint32_t sb = smem_u32(smem);
    float c[4][4][4] = {};

    auto load_stage = [&](int i, int buf) {
        int k0 = i * 32;
        uint32_t dst = sb + buf * 40960;
        #pragma unroll
        for (int it = 0; it < 8; it++) {
            int idx = t + it * 256;
            int region = idx >> 10, part = (idx >> 9) & 1;
            int row = (idx >> 2) & 127, seg = idx & 3;
            const __nv_bfloat16* gp;
            uint32_t s;
            if (region == 0) {
                gp = (part ? g_hlo : g_hhi) + (size_t)(m0 + row) * HID + k0 + seg * 8;
                s = dst + part * 10240 + row * 80 + seg * 16;
            } else {
                gp = (part ? g_Wmu_lo : g_Wmu_hi) + (size_t)(n0 + row) * HID + k0 + seg * 8;
                s = dst + 20480 + part * 10240 + row * 80 + seg * 16;
            }
            CPA16(s, gp);
        }
        CPC();
    };

    const int NS = HID / 32;
    load_stage(0, 0); load_stage(1, 1);
    for (int i = 0; i < NS; i++) {
        int buf = i % 3;
        if (i + 2 < NS) load_stage(i + 2, (i + 2) % 3); else CPC();
        CPW(2);
        __syncthreads();
        uint32_t As = sb + buf * 40960, Bs = As + 20480;
        COMPUTE_HL_128x128(As, Bs);
        __syncthreads();
    }

    const int gr = lane >> 2, gc = (lane & 3) * 2;
    #pragma unroll
    for (int mt = 0; mt < 4; mt++)
        #pragma unroll
        for (int half = 0; half < 2; half++) {
            int row = m0 + wm * 64 + mt * 16 + gr + half * 8;
            #pragma unroll
            for (int nt = 0; nt < 4; nt++) {
                int ng = n0 + wn * 32 + nt * 8 + gc;
                float2 o;
                o.x = c[mt][nt][half * 2]     + mu[ng];
                o.y = c[mt][nt][half * 2 + 1] + mu[ng + 1];
                *(float2*)(mu_out + (size_t)row * HID + ng) = o;
            }
        }
}

// ---------------- k3: 3-gate GEMM (K=256, single-pass) + dynamics epilogue --
__global__ __launch_bounds__(256, 1) void k3_mma(
    const float* __restrict__ h, const float* __restrict__ v,
    const float* __restrict__ b_out, const float* __restrict__ mu_out,
    float* __restrict__ h_next, float* __restrict__ v_next)
{
    extern __shared__ char smem[];
    const int t = threadIdx.x, lane = t & 31, wid = t >> 5;
    const int wm = wid >> 2, wn = wid & 3;
    const int m0 = blockIdx.y * 128, n0 = blockIdx.x * 64;
    uint32_t sb = smem_u32(smem);
    float c[3][4][2][4] = {};

    auto load_stage = [&](int i, int buf) {
        int k0 = i * 32;
        uint32_t dst = sb + buf * 25600;
        #pragma unroll
        for (int it = 0; it < 5; it++) {
            int idx = t + it * 256;
            const __nv_bfloat16* gp;
            uint32_t s;
            if (idx < 512) {
                int row = idx >> 2, seg = idx & 3;
                gp = g_chi + (size_t)(m0 + row) * CD + k0 + seg * 8;
                s = dst + row * 80 + seg * 16;
            } else {
                int j = idx - 512, row = j >> 2, seg = j & 3;
                int g = row >> 6, rg = row & 63;
                gp = g_Wout_hi + (size_t)(g * HID + n0 + rg) * CD + k0 + seg * 8;
                s = dst + 10240 + g * 5120 + rg * 80 + seg * 16;
            }
            CPA16(s, gp);
        }
        CPC();
    };

    const int NS = CD / 32;  // 8
    load_stage(0, 0); load_stage(1, 1);
    for (int i = 0; i < NS; i++) {
        int buf = i % 3;
        if (i + 2 < NS) load_stage(i + 2, (i + 2) % 3); else CPC();
        CPW(2);
        __syncthreads();
        uint32_t As = sb + buf * 25600, Bs = As + 10240;
        #pragma unroll
        for (int kk = 0; kk < 32; kk += 16) {
            uint32_t ah[4][4];
            uint32_t aoff = As + wm * 5120 + (lane & 15) * 80 + (lane >> 4) * 16 + kk * 2;
            #pragma unroll
            for (int mt = 0; mt < 4; mt++) ldsm4(ah[mt], aoff + mt * 1280);
            uint32_t boff = Bs + wn * 1280 + ((lane & 7) + ((lane >> 3) & 1) * 8) * 80
                            + (lane >> 4) * 16 + kk * 2;
            #pragma unroll
            for (int g = 0; g < 3; g++) {
                uint32_t bh[4];
                ldsm4(bh, boff + g * 5120);
                #pragma unroll
                for (int mt = 0; mt < 4; mt++) {
                    mma_bf16(c[g][mt][0], ah[mt], bh[0], bh[2]);
                    mma_bf16(c[g][mt][1], ah[mt], bh[1], bh[3]);
                }
            }
        }
        __syncthreads();
    }

    const int gr = lane >> 2, gc = (lane & 3) * 2;
    #pragma unroll
    for (int mt = 0; mt < 4; mt++)
        #pragma unroll
        for (int half = 0; half < 2; half++) {
            int row = m0 + wm * 64 + mt * 16 + gr + half * 8;
            size_t rb = (size_t)row * HID;
            #pragma unroll
            for (int nt = 0; nt < 2; nt++) {
                int ng = n0 + wn * 16 + nt * 8 + gc;
                size_t o = rb + ng;
                float a0 = c[0][mt][nt][half*2]   + b_out[ng];
                float a1 = c[0][mt][nt][half*2+1] + b_out[ng + 1];
                float b0 = c[1][mt][nt][half*2]   + b_out[HID + ng];
                float b1 = c[1][mt][nt][half*2+1] + b_out[HID + ng + 1];
                float g0 = c[2][mt][nt][half*2]   + b_out[2 * HID + ng];
                float g1 = c[2][mt][nt][half*2+1] + b_out[2 * HID + ng + 1];
                float al0 = sigm(a0), al1 = sigm(a1);
                float be0 = fminf(fmaxf(b0, 0.f) + log1pf(expf(-fabsf(b0))), 2.0f);
                float be1 = fminf(fmaxf(b1, 0.f) + log1pf(expf(-fabsf(b1))), 2.0f);
                float gt0 = sigm(g0), gt1 = sigm(g1);
                float2 hv = *(const float2*)(h + o);
                float2 vv = *(const float2*)(v + o);
                float2 mc = *(const float2*)(mu_out + o);
                float vn0 = al0 * vv.x - be0 * (hv.x - mc.x);
                float vn1 = al1 * vv.y - be1 * (hv.y - mc.y);
                vn0 = fminf(fmaxf(vn0, -10.f), 10.f);
                vn1 = fminf(fmaxf(vn1, -10.f), 10.f);
                float2 hn = { hv.x + 0.1f * gt0 * vn0, hv.y + 0.1f * gt1 * vn1 };
                float2 vn = { vn0, vn1 };
                *(float2*)(h_next + o) = hn;
                *(float2*)(v_next + o) = vn;
            }
        }
}

// ---------------- launch ----------------
extern "C" void kernel_launch(void* const* d_in, const int* in_sizes, int n_in,
                              void* d_out, int out_size)
{
    const float* h     = (const float*)d_in[0];
    const float* v     = (const float*)d_in[1];
    const float* W_in  = (const float*)d_in[2];
    const float* b_in  = (const float*)d_in[3];
    const float* W_out = (const float*)d_in[4];
    const float* b_out = (const float*)d_in[5];
    const float* W_mu  = (const float*)d_in[6];
    const float* mu    = (const float*)d_in[7];

    float* out    = (float*)d_out;
    float* h_next = out;
    float* v_next = out + (size_t)NB * HID;
    float* mu_out = out + 2 * (size_t)NB * HID;

    cudaFuncSetAttribute(k1_mma, cudaFuncAttributeMaxDynamicSharedMemorySize, 3 * 20480);
    cudaFuncSetAttribute(k2_mma, cudaFuncAttributeMaxDynamicSharedMemorySize, 3 * 40960);
    cudaFuncSetAttribute(k3_mma, cudaFuncAttributeMaxDynamicSharedMemorySize, 3 * 25600);

    __nv_bfloat16 *hhi, *hlo, *vhi, *wmh, *wml, *wih, *woh;
    cudaGetSymbolAddress((void**)&hhi, g_hhi);    cudaGetSymbolAddress((void**)&hlo, g_hlo);
    cudaGetSymbolAddress((void**)&vhi, g_vhi);
    cudaGetSymbolAddress((void**)&wmh, g_Wmu_hi); cudaGetSymbolAddress((void**)&wml, g_Wmu_lo);
    cudaGetSymbolAddress((void**)&wih, g_Win_hi); cudaGetSymbolAddress((void**)&woh, g_Wout_hi);

    const int nh  = NB * HID;
    const int nwm = HID * HID;
    const int nwi = CD * KC;
    const int nwo = 3 * HID * CD;
    k_conv   <<<nh  / 4 / 256, 256>>>(h,     hhi, hlo, nh);
    k_conv_hi<<<nh  / 4 / 256, 256>>>(v,     vhi, nh);
    k_conv   <<<nwm / 4 / 256, 256>>>(W_mu,  wmh, wml, nwm);
    k_conv_hi<<<nwi / 4 / 256, 256>>>(W_in,  wih, nwi);
    k_conv_hi<<<nwo / 4 / 256, 256>>>(W_out, woh, nwo);

    k1_mma<<<dim3(CD / 128,  NB / 128), 256, 3 * 20480>>>(b_in);
    k2_mma<<<dim3(HID / 128, NB / 128), 256, 3 * 40960>>>(mu, mu_out);
    k3_mma<<<dim3(HID / 64,  NB / 128), 256, 3 * 25600>>>(h, v, b_out, mu_out,
                                                          h_next, v_next);
}